// round 7
// baseline (speedup 1.0000x reference)
#include <cuda_runtime.h>
#include <cstdint>

#define THREADS   256
#define TILE_ROWS 512
#define NCTA      1024

__device__ __forceinline__ uint32_t smem_u32(const void* p) {
    return (uint32_t)__cvta_generic_to_shared(p);
}

__global__ __launch_bounds__(THREADS, 8)
void mlp321_kernel(const float* __restrict__ x,
                   const float* __restrict__ W1, const float* __restrict__ b1,
                   const float* __restrict__ W2, const float* __restrict__ b2,
                   const float* __restrict__ W3, const float* __restrict__ b3,
                   float* __restrict__ out,     // [B]
                   float* __restrict__ h1_out,  // [B,3]
                   float* __restrict__ h2_out,  // [B,2]
                   int tiles_per_cta)
{
    // ping-pong staging: 2 x 12 KB
    __shared__ __align__(16) float s_out[2][TILE_ROWS];          // 2 x 2 KB
    __shared__ __align__(16) float s_h1[2][TILE_ROWS * 3];       // 2 x 6 KB
    __shared__ __align__(16) float s_h2[2][TILE_ROWS * 2];       // 2 x 4 KB

    int tid = threadIdx.x;

    // tiny weights: broadcast L1 hits (hoisted once per CTA lifetime)
    float w1[6], bb1[3], w2[6], bb2[2], w3[2], bb3;
#pragma unroll
    for (int i = 0; i < 6; i++) w1[i] = __ldg(W1 + i);
#pragma unroll
    for (int i = 0; i < 3; i++) bb1[i] = __ldg(b1 + i);
#pragma unroll
    for (int i = 0; i < 6; i++) w2[i] = __ldg(W2 + i);
#pragma unroll
    for (int i = 0; i < 2; i++) bb2[i] = __ldg(b2 + i);
#pragma unroll
    for (int i = 0; i < 2; i++) w3[i] = __ldg(W3 + i);
    bb3 = __ldg(b3);

    int r0 = tid * 2;                       // 2 consecutive rows per thread
    long long first_tile = (long long)blockIdx.x * tiles_per_cta;

    for (int it = 0; it < tiles_per_cta; ++it) {
        int p = it & 1;
        long long tbase = (first_tile + it) * TILE_ROWS;

        // ---- make sure buffer p's previous TMA (issued at it-2) has read it out ----
        if (it >= 2 && tid == 0) {
            asm volatile("cp.async.bulk.wait_group.read 1;" ::: "memory");
        }
        __syncthreads();

        // ---- load 2 rows of x: 1x LDG.128, fully coalesced ----
        float4 xa = __ldg(reinterpret_cast<const float4*>(x + (tbase + r0) * 2));
        float x0[2] = {xa.x, xa.z};
        float x1[2] = {xa.y, xa.w};

        float h1v[2][3], h2v[2][2], ov[2];
#pragma unroll
        for (int e = 0; e < 2; e++) {
#pragma unroll
            for (int j = 0; j < 3; j++) {
                float v = fmaf(x0[e], w1[j * 2 + 0], fmaf(x1[e], w1[j * 2 + 1], bb1[j]));
                h1v[e][j] = fmaxf(v, 0.0f);
            }
#pragma unroll
            for (int j = 0; j < 2; j++) {
                float v = bb2[j];
#pragma unroll
                for (int k = 0; k < 3; k++) v = fmaf(h1v[e][k], w2[j * 3 + k], v);
                h2v[e][j] = fmaxf(v, 0.0f);
            }
            float z = fmaf(h2v[e][0], w3[0], fmaf(h2v[e][1], w3[1], bb3));
            ov[e] = 1.0f / (1.0f + __expf(-z));
        }

        // ---- stage into buffer p (8B/16B vector STS) ----
        reinterpret_cast<float2*>(&s_out[p][r0])[0] = make_float2(ov[0], ov[1]);

        float2* h1p = reinterpret_cast<float2*>(&s_h1[p][r0 * 3]);  // 8B-aligned
        h1p[0] = make_float2(h1v[0][0], h1v[0][1]);
        h1p[1] = make_float2(h1v[0][2], h1v[1][0]);
        h1p[2] = make_float2(h1v[1][1], h1v[1][2]);

        reinterpret_cast<float4*>(&s_h2[p][r0 * 2])[0] =
            make_float4(h2v[0][0], h2v[0][1], h2v[1][0], h2v[1][1]);

        // ---- publish buffer p to the async proxy, then kick TMA ----
        asm volatile("fence.proxy.async.shared::cta;" ::: "memory");
        __syncthreads();

        if (tid == 0) {
            uint32_t so = smem_u32(&s_out[p][0]);
            uint32_t s1 = smem_u32(&s_h1[p][0]);
            uint32_t s2 = smem_u32(&s_h2[p][0]);
            asm volatile(
                "cp.async.bulk.global.shared::cta.bulk_group [%0], [%1], %2;"
                :: "l"(h1_out + tbase * 3), "r"(s1), "r"((uint32_t)(TILE_ROWS * 12)) : "memory");
            asm volatile(
                "cp.async.bulk.global.shared::cta.bulk_group [%0], [%1], %2;"
                :: "l"(h2_out + tbase * 2), "r"(s2), "r"((uint32_t)(TILE_ROWS * 8)) : "memory");
            asm volatile(
                "cp.async.bulk.global.shared::cta.bulk_group [%0], [%1], %2;"
                :: "l"(out + tbase), "r"(so), "r"((uint32_t)(TILE_ROWS * 4)) : "memory");
            asm volatile("cp.async.bulk.commit_group;" ::: "memory");
        }
        // no trailing sync: next iteration's wait_group + syncthreads covers reuse
    }

    // drain all outstanding bulk stores before CTA exit
    if (tid == 0) {
        asm volatile("cp.async.bulk.wait_group 0;" ::: "memory");
    }
}

extern "C" void kernel_launch(void* const* d_in, const int* in_sizes, int n_in,
                              void* d_out, int out_size)
{
    const float* x  = (const float*)d_in[0];
    const float* W1 = (const float*)d_in[1];
    const float* b1 = (const float*)d_in[2];
    const float* W2 = (const float*)d_in[3];
    const float* b2 = (const float*)d_in[4];
    const float* W3 = (const float*)d_in[5];
    const float* b3 = (const float*)d_in[6];

    int B = in_sizes[0] / 2;   // x is [B,2]
    float* out    = (float*)d_out;                 // [B]
    float* h1_out = out + B;                       // [B,3]
    float* h2_out = h1_out + (long long)B * 3;     // [B,2]

    int ntiles = B / TILE_ROWS;                    // 16384
    int tiles_per_cta = ntiles / NCTA;             // 16

    mlp321_kernel<<<NCTA, THREADS>>>(x, W1, b1, W2, b2, W3, b3,
                                     out, h1_out, h2_out, tiles_per_cta);
}

// round 8
// speedup vs baseline: 1.1452x; 1.1452x over previous
#include <cuda_runtime.h>
#include <cstdint>

#define ROWS_PER_BLOCK 1024
#define THREADS 256

__device__ __forceinline__ uint32_t smem_u32(const void* p) {
    return (uint32_t)__cvta_generic_to_shared(p);
}

__global__ __launch_bounds__(THREADS, 8)
void mlp321_kernel(const float* __restrict__ x,
                   const float* __restrict__ W1, const float* __restrict__ b1,
                   const float* __restrict__ W2, const float* __restrict__ b2,
                   const float* __restrict__ W3, const float* __restrict__ b3,
                   float* __restrict__ out,     // [B]
                   float* __restrict__ h1_out,  // [B,3]
                   float* __restrict__ h2_out)  // [B,2]
{
    __shared__ __align__(16) float s_out[ROWS_PER_BLOCK];        //  4 KB
    __shared__ __align__(16) float s_h1[ROWS_PER_BLOCK * 3];     // 12 KB
    __shared__ __align__(16) float s_h2[ROWS_PER_BLOCK * 2];     //  8 KB

    int tid = threadIdx.x;
    long long base = (long long)blockIdx.x * ROWS_PER_BLOCK;

    // tiny weights: broadcast L1 hits
    float w1[6], bb1[3], w2[6], bb2[2], w3[2], bb3;
#pragma unroll
    for (int i = 0; i < 6; i++) w1[i] = __ldg(W1 + i);
#pragma unroll
    for (int i = 0; i < 3; i++) bb1[i] = __ldg(b1 + i);
#pragma unroll
    for (int i = 0; i < 6; i++) w2[i] = __ldg(W2 + i);
#pragma unroll
    for (int i = 0; i < 2; i++) bb2[i] = __ldg(b2 + i);
#pragma unroll
    for (int i = 0; i < 2; i++) w3[i] = __ldg(W3 + i);
    bb3 = __ldg(b3);

    // strided row mapping: thread t handles rows t, t+256, t+512, t+768.
    float2 xv[4];
#pragma unroll
    for (int r = 0; r < 4; r++) {
        int row = tid + r * THREADS;
        xv[r] = __ldg(reinterpret_cast<const float2*>(x + (base + row) * 2));
    }

#pragma unroll
    for (int r = 0; r < 4; r++) {
        int row = tid + r * THREADS;
        float x0 = xv[r].x, x1 = xv[r].y;

        float h1v[3];
#pragma unroll
        for (int j = 0; j < 3; j++) {
            float v = fmaf(x0, w1[j * 2 + 0], fmaf(x1, w1[j * 2 + 1], bb1[j]));
            h1v[j] = fmaxf(v, 0.0f);
        }
        float h2v[2];
#pragma unroll
        for (int j = 0; j < 2; j++) {
            float v = bb2[j];
#pragma unroll
            for (int k = 0; k < 3; k++) v = fmaf(h1v[k], w2[j * 3 + k], v);
            h2v[j] = fmaxf(v, 0.0f);
        }
        float z = fmaf(h2v[0], w3[0], fmaf(h2v[1], w3[1], bb3));
        float o = 1.0f / (1.0f + __expf(-z));

        s_h1[row * 3 + 0] = h1v[0];
        s_h1[row * 3 + 1] = h1v[1];
        s_h1[row * 3 + 2] = h1v[2];
        s_h2[row * 2 + 0] = h2v[0];
        s_h2[row * 2 + 1] = h2v[1];
        s_out[row] = o;
    }

    // make generic-proxy smem writes visible to the async (TMA) proxy
    asm volatile("fence.proxy.async.shared::cta;" ::: "memory");
    __syncthreads();

    if (tid == 0) {
        uint32_t so = smem_u32(s_out), s1 = smem_u32(s_h1), s2 = smem_u32(s_h2);
        // L2 evict_first policy: the output stream is never re-read; keep x's
        // read stream resident instead of thrashing L2 with 192MB of writes.
        uint64_t pol;
        asm volatile("createpolicy.fractional.L2::evict_first.b64 %0, 1.0;" : "=l"(pol));
        asm volatile(
            "cp.async.bulk.global.shared::cta.bulk_group.L2::cache_hint [%0], [%1], %2, %3;"
            :: "l"(h1_out + base * 3), "r"(s1), "r"((uint32_t)(ROWS_PER_BLOCK * 12)), "l"(pol) : "memory");
        asm volatile(
            "cp.async.bulk.global.shared::cta.bulk_group.L2::cache_hint [%0], [%1], %2, %3;"
            :: "l"(h2_out + base * 2), "r"(s2), "r"((uint32_t)(ROWS_PER_BLOCK * 8)), "l"(pol) : "memory");
        asm volatile(
            "cp.async.bulk.global.shared::cta.bulk_group.L2::cache_hint [%0], [%1], %2, %3;"
            :: "l"(out + base), "r"(so), "r"((uint32_t)(ROWS_PER_BLOCK * 4)), "l"(pol) : "memory");
        asm volatile("cp.async.bulk.commit_group;" ::: "memory");
        // only wait until TMA has finished READING smem (safe for smem reuse);
        // do not wait for global write completion — shortens the CTA tail.
        asm volatile("cp.async.bulk.wait_group.read 0;" ::: "memory");
    }
}

extern "C" void kernel_launch(void* const* d_in, const int* in_sizes, int n_in,
                              void* d_out, int out_size)
{
    const float* x  = (const float*)d_in[0];
    const float* W1 = (const float*)d_in[1];
    const float* b1 = (const float*)d_in[2];
    const float* W2 = (const float*)d_in[3];
    const float* b2 = (const float*)d_in[4];
    const float* W3 = (const float*)d_in[5];
    const float* b3 = (const float*)d_in[6];

    int B = in_sizes[0] / 2;   // x is [B,2]
    float* out    = (float*)d_out;                 // [B]
    float* h1_out = out + B;                       // [B,3]
    float* h2_out = h1_out + (long long)B * 3;     // [B,2]

    int blocks = B / ROWS_PER_BLOCK;               // 8388608 / 1024 = 8192
    mlp321_kernel<<<blocks, THREADS>>>(x, W1, b1, W2, b2, W3, b3,
                                       out, h1_out, h2_out);
}

// round 9
// speedup vs baseline: 1.1796x; 1.0300x over previous
#include <cuda_runtime.h>
#include <cstdint>

#define ROWS_PER_BLOCK 1024
#define HALF_ROWS      512
#define THREADS        256

__device__ __forceinline__ uint32_t smem_u32(const void* p) {
    return (uint32_t)__cvta_generic_to_shared(p);
}

__device__ __forceinline__ float sigmoid_tanh(float z) {
    float t;
    asm("tanh.approx.f32 %0, %1;" : "=f"(t) : "f"(z * 0.5f));
    return fmaf(t, 0.5f, 0.5f);
}

__global__ __launch_bounds__(THREADS, 8)
void mlp321_kernel(const float* __restrict__ x,
                   const float* __restrict__ W1, const float* __restrict__ b1,
                   const float* __restrict__ W2, const float* __restrict__ b2,
                   const float* __restrict__ W3, const float* __restrict__ b3,
                   float* __restrict__ out,     // [B]
                   float* __restrict__ h1_out,  // [B,3]
                   float* __restrict__ h2_out)  // [B,2]
{
    __shared__ __align__(16) float s_out[ROWS_PER_BLOCK];        //  4 KB
    __shared__ __align__(16) float s_h1[ROWS_PER_BLOCK * 3];     // 12 KB
    __shared__ __align__(16) float s_h2[ROWS_PER_BLOCK * 2];     //  8 KB

    int tid = threadIdx.x;
    long long base = (long long)blockIdx.x * ROWS_PER_BLOCK;

    // tiny weights: broadcast L1 hits
    float w1[6], bb1[3], w2[6], bb2[2], w3[2], bb3;
#pragma unroll
    for (int i = 0; i < 6; i++) w1[i] = __ldg(W1 + i);
#pragma unroll
    for (int i = 0; i < 3; i++) bb1[i] = __ldg(b1 + i);
#pragma unroll
    for (int i = 0; i < 6; i++) w2[i] = __ldg(W2 + i);
#pragma unroll
    for (int i = 0; i < 2; i++) bb2[i] = __ldg(b2 + i);
#pragma unroll
    for (int i = 0; i < 2; i++) w3[i] = __ldg(W3 + i);
    bb3 = __ldg(b3);

    // batch ALL x loads up front (MLP=4), strided row mapping
    float2 xv[4];
#pragma unroll
    for (int r = 0; r < 4; r++) {
        int row = tid + r * THREADS;
        xv[r] = __ldg(reinterpret_cast<const float2*>(x + (base + row) * 2));
    }

    uint64_t pol;
    asm volatile("createpolicy.fractional.L2::evict_first.b64 %0, 1.0;" : "=l"(pol));

    // ================= HALF A: rows 0..511 =================
#pragma unroll
    for (int r = 0; r < 2; r++) {
        int row = tid + r * THREADS;
        float x0 = xv[r].x, x1 = xv[r].y;

        float h1v[3];
#pragma unroll
        for (int j = 0; j < 3; j++) {
            float v = fmaf(x0, w1[j * 2 + 0], fmaf(x1, w1[j * 2 + 1], bb1[j]));
            h1v[j] = fmaxf(v, 0.0f);
        }
        float h2v[2];
#pragma unroll
        for (int j = 0; j < 2; j++) {
            float v = bb2[j];
#pragma unroll
            for (int k = 0; k < 3; k++) v = fmaf(h1v[k], w2[j * 3 + k], v);
            h2v[j] = fmaxf(v, 0.0f);
        }
        float z = fmaf(h2v[0], w3[0], fmaf(h2v[1], w3[1], bb3));

        s_h1[row * 3 + 0] = h1v[0];
        s_h1[row * 3 + 1] = h1v[1];
        s_h1[row * 3 + 2] = h1v[2];
        s_h2[row * 2 + 0] = h2v[0];
        s_h2[row * 2 + 1] = h2v[1];
        s_out[row] = sigmoid_tanh(z);
    }

    asm volatile("fence.proxy.async.shared::cta;" ::: "memory");
    __syncthreads();

    // issue half-A TMA, do NOT wait — overlaps with half-B compute
    if (tid == 0) {
        asm volatile(
            "cp.async.bulk.global.shared::cta.bulk_group.L2::cache_hint [%0], [%1], %2, %3;"
            :: "l"(h1_out + base * 3), "r"(smem_u32(s_h1)),
               "r"((uint32_t)(HALF_ROWS * 12)), "l"(pol) : "memory");
        asm volatile(
            "cp.async.bulk.global.shared::cta.bulk_group.L2::cache_hint [%0], [%1], %2, %3;"
            :: "l"(h2_out + base * 2), "r"(smem_u32(s_h2)),
               "r"((uint32_t)(HALF_ROWS * 8)), "l"(pol) : "memory");
        asm volatile(
            "cp.async.bulk.global.shared::cta.bulk_group.L2::cache_hint [%0], [%1], %2, %3;"
            :: "l"(out + base), "r"(smem_u32(s_out)),
               "r"((uint32_t)(HALF_ROWS * 4)), "l"(pol) : "memory");
        asm volatile("cp.async.bulk.commit_group;" ::: "memory");
    }

    // ================= HALF B: rows 512..1023 =================
#pragma unroll
    for (int r = 2; r < 4; r++) {
        int row = tid + r * THREADS;
        float x0 = xv[r].x, x1 = xv[r].y;

        float h1v[3];
#pragma unroll
        for (int j = 0; j < 3; j++) {
            float v = fmaf(x0, w1[j * 2 + 0], fmaf(x1, w1[j * 2 + 1], bb1[j]));
            h1v[j] = fmaxf(v, 0.0f);
        }
        float h2v[2];
#pragma unroll
        for (int j = 0; j < 2; j++) {
            float v = bb2[j];
#pragma unroll
            for (int k = 0; k < 3; k++) v = fmaf(h1v[k], w2[j * 3 + k], v);
            h2v[j] = fmaxf(v, 0.0f);
        }
        float z = fmaf(h2v[0], w3[0], fmaf(h2v[1], w3[1], bb3));

        s_h1[row * 3 + 0] = h1v[0];
        s_h1[row * 3 + 1] = h1v[1];
        s_h1[row * 3 + 2] = h1v[2];
        s_h2[row * 2 + 0] = h2v[0];
        s_h2[row * 2 + 1] = h2v[1];
        s_out[row] = sigmoid_tanh(z);
    }

    asm volatile("fence.proxy.async.shared::cta;" ::: "memory");
    __syncthreads();

    if (tid == 0) {
        asm volatile(
            "cp.async.bulk.global.shared::cta.bulk_group.L2::cache_hint [%0], [%1], %2, %3;"
            :: "l"(h1_out + base * 3 + HALF_ROWS * 3), "r"(smem_u32(s_h1 + HALF_ROWS * 3)),
               "r"((uint32_t)(HALF_ROWS * 12)), "l"(pol) : "memory");
        asm volatile(
            "cp.async.bulk.global.shared::cta.bulk_group.L2::cache_hint [%0], [%1], %2, %3;"
            :: "l"(h2_out + base * 2 + HALF_ROWS * 2), "r"(smem_u32(s_h2 + HALF_ROWS * 2)),
               "r"((uint32_t)(HALF_ROWS * 8)), "l"(pol) : "memory");
        asm volatile(
            "cp.async.bulk.global.shared::cta.bulk_group.L2::cache_hint [%0], [%1], %2, %3;"
            :: "l"(out + base + HALF_ROWS), "r"(smem_u32(s_out + HALF_ROWS)),
               "r"((uint32_t)(HALF_ROWS * 4)), "l"(pol) : "memory");
        asm volatile("cp.async.bulk.commit_group;" ::: "memory");
        // wait only for smem reads of BOTH groups (safe for smem reuse)
        asm volatile("cp.async.bulk.wait_group.read 0;" ::: "memory");
    }
}

extern "C" void kernel_launch(void* const* d_in, const int* in_sizes, int n_in,
                              void* d_out, int out_size)
{
    const float* x  = (const float*)d_in[0];
    const float* W1 = (const float*)d_in[1];
    const float* b1 = (const float*)d_in[2];
    const float* W2 = (const float*)d_in[3];
    const float* b2 = (const float*)d_in[4];
    const float* W3 = (const float*)d_in[5];
    const float* b3 = (const float*)d_in[6];

    int B = in_sizes[0] / 2;   // x is [B,2]
    float* out    = (float*)d_out;                 // [B]
    float* h1_out = out + B;                       // [B,3]
    float* h2_out = h1_out + (long long)B * 3;     // [B,2]

    int blocks = B / ROWS_PER_BLOCK;               // 8388608 / 1024 = 8192
    mlp321_kernel<<<blocks, THREADS>>>(x, W1, b1, W2, b2, W3, b3,
                                       out, h1_out, h2_out);
}

// round 10
// speedup vs baseline: 1.1896x; 1.0085x over previous
#include <cuda_runtime.h>
#include <cstdint>

#define ROWS_PER_BLOCK 1024
#define STAGE_ROWS     256   // one stage = one r-iteration = 256 rows
#define THREADS        256

__device__ __forceinline__ uint32_t smem_u32(const void* p) {
    return (uint32_t)__cvta_generic_to_shared(p);
}

__device__ __forceinline__ float sigmoid_tanh(float z) {
    float t;
    asm("tanh.approx.f32 %0, %1;" : "=f"(t) : "f"(z * 0.5f));
    return fmaf(t, 0.5f, 0.5f);
}

__global__ __launch_bounds__(THREADS, 8)
void mlp321_kernel(const float* __restrict__ x,
                   const float* __restrict__ W1, const float* __restrict__ b1,
                   const float* __restrict__ W2, const float* __restrict__ b2,
                   const float* __restrict__ W3, const float* __restrict__ b3,
                   float* __restrict__ out,     // [B]
                   float* __restrict__ h1_out,  // [B,3]
                   float* __restrict__ h2_out)  // [B,2]
{
    __shared__ __align__(16) float s_out[ROWS_PER_BLOCK];        //  4 KB
    __shared__ __align__(16) float s_h1[ROWS_PER_BLOCK * 3];     // 12 KB
    __shared__ __align__(16) float s_h2[ROWS_PER_BLOCK * 2];     //  8 KB

    int tid = threadIdx.x;
    long long base = (long long)blockIdx.x * ROWS_PER_BLOCK;

    // tiny weights: broadcast L1 hits
    float w1[6], bb1[3], w2[6], bb2[2], w3[2], bb3;
#pragma unroll
    for (int i = 0; i < 6; i++) w1[i] = __ldg(W1 + i);
#pragma unroll
    for (int i = 0; i < 3; i++) bb1[i] = __ldg(b1 + i);
#pragma unroll
    for (int i = 0; i < 6; i++) w2[i] = __ldg(W2 + i);
#pragma unroll
    for (int i = 0; i < 2; i++) bb2[i] = __ldg(b2 + i);
#pragma unroll
    for (int i = 0; i < 2; i++) w3[i] = __ldg(W3 + i);
    bb3 = __ldg(b3);

    // batch ALL x loads up front (MLP=4), strided row mapping
    float2 xv[4];
#pragma unroll
    for (int r = 0; r < 4; r++) {
        int row = tid + r * THREADS;
        xv[r] = __ldg(reinterpret_cast<const float2*>(x + (base + row) * 2));
    }

    uint64_t pol;
    asm volatile("createpolicy.fractional.L2::evict_first.b64 %0, 1.0;" : "=l"(pol));

    // ---- 4 stages: compute 256 rows -> issue TMA (no wait) -> next stage ----
#pragma unroll
    for (int r = 0; r < 4; r++) {
        int row = tid + r * THREADS;
        float x0 = xv[r].x, x1 = xv[r].y;

        float h1v[3];
#pragma unroll
        for (int j = 0; j < 3; j++) {
            float v = fmaf(x0, w1[j * 2 + 0], fmaf(x1, w1[j * 2 + 1], bb1[j]));
            h1v[j] = fmaxf(v, 0.0f);
        }
        float h2v[2];
#pragma unroll
        for (int j = 0; j < 2; j++) {
            float v = bb2[j];
#pragma unroll
            for (int k = 0; k < 3; k++) v = fmaf(h1v[k], w2[j * 3 + k], v);
            h2v[j] = fmaxf(v, 0.0f);
        }
        float z = fmaf(h2v[0], w3[0], fmaf(h2v[1], w3[1], bb3));

        s_h1[row * 3 + 0] = h1v[0];
        s_h1[row * 3 + 1] = h1v[1];
        s_h1[row * 3 + 2] = h1v[2];
        s_h2[row * 2 + 0] = h2v[0];
        s_h2[row * 2 + 1] = h2v[1];
        s_out[row] = sigmoid_tanh(z);

        // publish this stage's 256 rows and kick its TMA group
        asm volatile("fence.proxy.async.shared::cta;" ::: "memory");
        __syncthreads();

        if (tid == 0) {
            long long sb = (long long)r * STAGE_ROWS;     // stage row offset
            asm volatile(
                "cp.async.bulk.global.shared::cta.bulk_group.L2::cache_hint [%0], [%1], %2, %3;"
                :: "l"(h1_out + (base + sb) * 3), "r"(smem_u32(s_h1 + sb * 3)),
                   "r"((uint32_t)(STAGE_ROWS * 12)), "l"(pol) : "memory");
            asm volatile(
                "cp.async.bulk.global.shared::cta.bulk_group.L2::cache_hint [%0], [%1], %2, %3;"
                :: "l"(h2_out + (base + sb) * 2), "r"(smem_u32(s_h2 + sb * 2)),
                   "r"((uint32_t)(STAGE_ROWS * 8)), "l"(pol) : "memory");
            asm volatile(
                "cp.async.bulk.global.shared::cta.bulk_group.L2::cache_hint [%0], [%1], %2, %3;"
                :: "l"(out + base + sb), "r"(smem_u32(s_out + sb)),
                   "r"((uint32_t)(STAGE_ROWS * 4)), "l"(pol) : "memory");
            asm volatile("cp.async.bulk.commit_group;" ::: "memory");
        }
    }

    // wait only for smem reads of all 4 groups (safe: smem freed at exit)
    if (tid == 0) {
        asm volatile("cp.async.bulk.wait_group.read 0;" ::: "memory");
    }
}

extern "C" void kernel_launch(void* const* d_in, const int* in_sizes, int n_in,
                              void* d_out, int out_size)
{
    const float* x  = (const float*)d_in[0];
    const float* W1 = (const float*)d_in[1];
    const float* b1 = (const float*)d_in[2];
    const float* W2 = (const float*)d_in[3];
    const float* b2 = (const float*)d_in[4];
    const float* W3 = (const float*)d_in[5];
    const float* b3 = (const float*)d_in[6];

    int B = in_sizes[0] / 2;   // x is [B,2]
    float* out    = (float*)d_out;                 // [B]
    float* h1_out = out + B;                       // [B,3]
    float* h2_out = h1_out + (long long)B * 3;     // [B,2]

    int blocks = B / ROWS_PER_BLOCK;               // 8388608 / 1024 = 8192
    mlp321_kernel<<<blocks, THREADS>>>(x, W1, b1, W2, b2, W3, b3,
                                       out, h1_out, h2_out);
}